// round 11
// baseline (speedup 1.0000x reference)
#include <cuda_runtime.h>

#define BATCH  64
#define SEQ    256
#define EMBED  512
#define HIDDEN 1024
#define G4     4096
#define BT     (BATCH * SEQ)
#define NCTA   128
#define CLUSTER 4

// ---------------- scratch ----------------
// packed h: [t][k8 0..127][mgroup 0..3][lane 0..31][slot 0..3]  (65536 floats per t)
__device__ __align__(256) float g_pre  [(size_t)BT * G4];
__device__ __align__(256) float g_hpack[(size_t)(SEQ + 1) * 65536];
__device__ __align__(256) float g_hist [(size_t)BT * HIDDEN];
__device__ unsigned g_sync;

// ---------------- tf32 helpers ----------------
__device__ __forceinline__ unsigned f2tf(float f) {
    unsigned u; asm("cvt.rna.tf32.f32 %0, %1;" : "=r"(u) : "f"(f)); return u;
}
__device__ __forceinline__ void mma8(float* c, unsigned a0, unsigned a1,
                                     unsigned a2, unsigned a3,
                                     unsigned b0, unsigned b1) {
    asm volatile(
        "mma.sync.aligned.m16n8k8.row.col.f32.tf32.tf32.f32 "
        "{%0,%1,%2,%3},{%4,%5,%6,%7},{%8,%9},{%0,%1,%2,%3};"
        : "+f"(c[0]), "+f"(c[1]), "+f"(c[2]), "+f"(c[3])
        : "r"(a0), "r"(a1), "r"(a2), "r"(a3), "r"(b0), "r"(b1));
}
__device__ __forceinline__ void sts_cluster_f2(unsigned addr, float x, float y) {
    unsigned long long v = (unsigned long long)__float_as_uint(x) |
                           ((unsigned long long)__float_as_uint(y) << 32);
    asm volatile("st.shared::cluster.b64 [%0], %1;" :: "r"(addr), "l"(v) : "memory");
}

// ---------------------------------------------------------------------------
// tf32 GEMM: C[M,N] = A[M,K] @ B[N,K]^T (+bias1+bias2), block 128x128x32,
// 8 warps as 2(m) x 4(n), warp tile 64x32.
// perm: 0 none; 1: out_row=(m&255)*64+(m>>8); 2: out_row=(m&63)*256+(m>>6).
// ---------------------------------------------------------------------------
__global__ __launch_bounds__(256, 2) void gemm_tf32(
    const float* __restrict__ A, int lda,
    const float* __restrict__ B, int ldb,
    float* __restrict__ C, int ldc, int K,
    const float* __restrict__ bias1, const float* __restrict__ bias2,
    int perm)
{
    __shared__ unsigned As[128][36];
    __shared__ unsigned Bs[128][36];
    const int tid = threadIdx.x, w = tid >> 5, lane = tid & 31;
    const int g = lane >> 2, cq = lane & 3;
    const int wm = w >> 2;
    const int wn = w & 3;
    const long m0 = (long)blockIdx.x * 128, n0 = (long)blockIdx.y * 128;

    float acc[4][4][4];
#pragma unroll
    for (int mi = 0; mi < 4; mi++)
#pragma unroll
        for (int ni = 0; ni < 4; ni++)
#pragma unroll
            for (int e = 0; e < 4; e++) acc[mi][ni][e] = 0.f;

    const int srow = tid >> 3, scol = (tid & 7) * 4;

    for (int k0 = 0; k0 < K; k0 += 32) {
#pragma unroll
        for (int p = 0; p < 4; p++) {
            int r = p * 32 + srow;
            float4 v = *(const float4*)(A + (size_t)(m0 + r) * lda + k0 + scol);
            unsigned* d = &As[r][scol];
            d[0] = f2tf(v.x); d[1] = f2tf(v.y); d[2] = f2tf(v.z); d[3] = f2tf(v.w);
        }
#pragma unroll
        for (int p = 0; p < 4; p++) {
            int r = p * 32 + srow;
            float4 v = *(const float4*)(B + (size_t)(n0 + r) * ldb + k0 + scol);
            unsigned* d = &Bs[r][scol];
            d[0] = f2tf(v.x); d[1] = f2tf(v.y); d[2] = f2tf(v.z); d[3] = f2tf(v.w);
        }
        __syncthreads();
#pragma unroll
        for (int kk = 0; kk < 32; kk += 8) {
            unsigned a[4][4], b[4][2];
#pragma unroll
            for (int mi = 0; mi < 4; mi++) {
                int rb = wm * 64 + mi * 16 + g;
                a[mi][0] = As[rb][kk + cq];
                a[mi][1] = As[rb + 8][kk + cq];
                a[mi][2] = As[rb][kk + cq + 4];
                a[mi][3] = As[rb + 8][kk + cq + 4];
            }
#pragma unroll
            for (int ni = 0; ni < 4; ni++) {
                int nb = wn * 32 + ni * 8 + g;
                b[ni][0] = Bs[nb][kk + cq];
                b[ni][1] = Bs[nb][kk + cq + 4];
            }
#pragma unroll
            for (int mi = 0; mi < 4; mi++)
#pragma unroll
                for (int ni = 0; ni < 4; ni++)
                    mma8(acc[mi][ni], a[mi][0], a[mi][1], a[mi][2], a[mi][3],
                         b[ni][0], b[ni][1]);
        }
        __syncthreads();
    }

#pragma unroll
    for (int ni = 0; ni < 4; ni++) {
        long col = n0 + wn * 32 + ni * 8 + 2 * cq;
        float bv0 = 0.f, bv1 = 0.f;
        if (bias1) { bv0 += bias1[col]; bv1 += bias1[col + 1]; }
        if (bias2) { bv0 += bias2[col]; bv1 += bias2[col + 1]; }
#pragma unroll
        for (int mi = 0; mi < 4; mi++) {
            long r0 = m0 + wm * 64 + mi * 16 + g;
            long r1 = r0 + 8;
            long p0 = (perm == 1) ? (r0 & 255) * 64 + (r0 >> 8)
                    : (perm == 2) ? (r0 & 63) * 256 + (r0 >> 6) : r0;
            long p1 = (perm == 1) ? (r1 & 255) * 64 + (r1 >> 8)
                    : (perm == 2) ? (r1 & 63) * 256 + (r1 >> 6) : r1;
            *(float2*)(C + p0 * ldc + col) =
                make_float2(acc[mi][ni][0] + bv0, acc[mi][ni][1] + bv1);
            *(float2*)(C + p1 * ldc + col) =
                make_float2(acc[mi][ni][2] + bv0, acc[mi][ni][3] + bv1);
        }
    }
}

// ---------------------------------------------------------------------------
__global__ void init_kernel()
{
    int idx = blockIdx.x * blockDim.x + threadIdx.x;   // 65536 threads
    g_hpack[idx] = 0.f;                                // h_0 block (packed) = 0
    if (idx == 0) g_sync = 0;
}

// ---------------------------------------------------------------------------
// Persistent LSTM recurrence, cluster K-split edition.
// 128 CTAs = 32 clusters(4). CTA (g = bid>>2, r = bid&3):
//   owns units [32g,32g+32) (N = 128 gate rows), K-slice k8 in [32r,32r+32).
// Per step: copy 64KB h-slice to smem (contiguous; layout is k8-major) ->
// warp(2m x 4n; warp wn = gate wn) tf32 mma from smem -> K-partials exchanged
// across cluster via DSMEM (rank d owns batch [16d,16d+16)) -> cluster.sync ->
// fused cell update -> packed h write -> red.release/ld.acquire grid barrier.
// h L2 traffic: 8MB/step (was 32MB).
// ---------------------------------------------------------------------------
#define WP_WORDS   32768                       // 128 KB packed W_hh B-frags
#define AH_FLOATS  16384                       // 64 KB h slice
#define XCH_FLOATS (4 * 16 * 128)              // 32 KB partial exchange
#define WP_OFF   0
#define AH_OFF   (WP_WORDS * 4)
#define XCH_OFF  (AH_OFF + AH_FLOATS * 4)
#define CS_OFF   (XCH_OFF + XCH_FLOATS * 4)
#define SM_BYTES (CS_OFF + 512 * 4)            // 231424 B

__global__ __launch_bounds__(256, 1) __cluster_dims__(CLUSTER, 1, 1)
void lstm_persistent(const float* __restrict__ pre, const float* __restrict__ Whh)
{
    extern __shared__ unsigned char smraw[];
    unsigned* Wp  = (unsigned*)(smraw + WP_OFF);
    float*    Ah  = (float*)(smraw + AH_OFF);
    float*    Xch = (float*)(smraw + XCH_OFF);   // [src_rank4][b'16][n128]
    float*    csm = (float*)(smraw + CS_OFF);    // [512]

    const int bid = blockIdx.x, tid = threadIdx.x;
    const int g = bid >> 2;          // unit group: units [32g, 32g+32)
    const int r = bid & 3;           // cluster rank = K-quarter
    const int w = tid >> 5, lane = tid & 31;
    const int lg = lane >> 2, cq = lane & 3;
    const int wm = w & 1, wn = w >> 1;   // warp tile: m-half x gate

    unsigned smem_base;
    asm("{ .reg .u64 t; cvta.to.shared.u64 t, %1; cvt.u32.u64 %0, t; }"
        : "=r"(smem_base) : "l"(smraw));

    // ---- one-time: pack this CTA's W_hh [128 rows x 256 K] as B-frags ----
    // word idx = (((k8l*4 + wn)*4 + ni)*32 + lane)*2 + hh
    for (int idx = tid; idx < WP_WORDS; idx += 256) {
        int hh  = idx & 1;
        int l   = (idx >> 1) & 31;
        int ni  = (idx >> 6) & 3;
        int wnp = (idx >> 8) & 3;
        int k8l = idx >> 10;
        int k    = (32 * r + k8l) * 8 + hh * 4 + (l & 3);
        int grow = wnp * 1024 + 32 * g + 8 * ni + (l >> 2);
        Wp[idx] = f2tf(Whh[(size_t)grow * 1024 + k]);
    }
    csm[tid] = 0.f; csm[tid + 256] = 0.f;
    __syncthreads();
    asm volatile("barrier.cluster.arrive.aligned;" ::: "memory");
    asm volatile("barrier.cluster.wait.aligned;" ::: "memory");

    // DSMEM addresses of Xch in dest ranks d = 2*wm + mi
    unsigned xch_u32 = smem_base + XCH_OFF;
    unsigned peer[2];
#pragma unroll
    for (int mi = 0; mi < 2; mi++) {
        int d = 2 * wm + mi;
        asm("mapa.shared::cluster.u32 %0, %1, %2;"
            : "=r"(peer[mi]) : "r"(xch_u32), "r"(d));
    }

    // cell assignments: cell q idx = tid + 256q -> b'=idx>>5, u=idx&31
    const int bq0 = tid >> 5, uu = tid & 31;
    const int bq1 = (tid + 256) >> 5;
    const int b0 = 16 * r + bq0, b1 = 16 * r + bq1;
    const int ug = 32 * g + uu;

    unsigned* syncp = &g_sync;

    for (int t = 0; t < SEQ; t++) {
        // pre-gate prefetch (coalesced 128B rows)
        const float* pp0 = pre + ((size_t)t * 64 + b0) * G4 + ug;
        const float* pp1 = pre + ((size_t)t * 64 + b1) * G4 + ug;
        float p0i = pp0[0], p0f = pp0[1024], p0g = pp0[2048], p0o = pp0[3072];
        float p1i = pp1[0], p1f = pp1[1024], p1g = pp1[2048], p1o = pp1[3072];

        // stage this rank's 64KB h slice (contiguous in packed layout)
        const float4* src = (const float4*)(g_hpack + (size_t)t * 65536 +
                                            (size_t)r * AH_FLOATS);
        float4* dst = (float4*)Ah;
#pragma unroll
        for (int i = 0; i < 16; i++) dst[tid + 256 * i] = src[tid + 256 * i];
        __syncthreads();

        float acc[2][4][4];
#pragma unroll
        for (int mi = 0; mi < 2; mi++)
#pragma unroll
            for (int ni = 0; ni < 4; ni++)
#pragma unroll
                for (int e = 0; e < 4; e++) acc[mi][ni][e] = 0.f;

#pragma unroll 4
        for (int k8l = 0; k8l < 32; k8l++) {
            float4 a0 = *(const float4*)&Ah[((k8l * 4 + 2 * wm) * 32 + lane) * 4];
            float4 a1 = *(const float4*)&Ah[((k8l * 4 + 2 * wm + 1) * 32 + lane) * 4];
            uint2 bf[4];
#pragma unroll
            for (int ni = 0; ni < 4; ni++)
                bf[ni] = *(const uint2*)&Wp[(((k8l * 4 + wn) * 4 + ni) * 32 + lane) * 2];
#pragma unroll
            for (int ni = 0; ni < 4; ni++) {
                mma8(acc[0][ni],
                     __float_as_uint(a0.x), __float_as_uint(a0.y),
                     __float_as_uint(a0.z), __float_as_uint(a0.w),
                     bf[ni].x, bf[ni].y);
                mma8(acc[1][ni],
                     __float_as_uint(a1.x), __float_as_uint(a1.y),
                     __float_as_uint(a1.z), __float_as_uint(a1.w),
                     bf[ni].x, bf[ni].y);
            }
        }

        // scatter K-partials to cluster owners (rank d owns batch [16d,+16))
        // m = 32wm + 16mi + lg (+8): owner d = 2wm+mi, row-in-buf = lg (+8)
#pragma unroll
        for (int mi = 0; mi < 2; mi++) {
#pragma unroll
            for (int ni = 0; ni < 4; ni++) {
                int c = 32 * wn + 8 * ni + 2 * cq;
                unsigned o0 = peer[mi] + (unsigned)(r * 2048 + lg * 128 + c) * 4;
                sts_cluster_f2(o0, acc[mi][ni][0], acc[mi][ni][1]);
                sts_cluster_f2(o0 + 8 * 128 * 4, acc[mi][ni][2], acc[mi][ni][3]);
            }
        }
        asm volatile("barrier.cluster.arrive.aligned;" ::: "memory");
        asm volatile("barrier.cluster.wait.aligned;" ::: "memory");

        // fused cell update: 2 cells/thread (batch-quarter x 32 units)
#pragma unroll
        for (int q = 0; q < 2; q++) {
            int bq = q ? bq1 : bq0;
            int b  = q ? b1 : b0;
            float gi = q ? p1i : p0i, gf = q ? p1f : p0f;
            float gg = q ? p1g : p0g, go = q ? p1o : p0o;
#pragma unroll
            for (int s = 0; s < 4; s++) {
                const float* xr = &Xch[s * 2048 + bq * 128];
                gi += xr[uu]; gf += xr[32 + uu];
                gg += xr[64 + uu]; go += xr[96 + uu];
            }
            int ci = q * 256 + tid;
            float cc = csm[ci];
            float iv = 1.f / (1.f + __expf(-gi));
            float fv = 1.f / (1.f + __expf(-gf));
            float gv = tanhf(gg);
            float ov = 1.f / (1.f + __expf(-go));
            cc = fv * cc + iv * gv;
            csm[ci] = cc;
            float hv = ov * tanhf(cc);
            float hq = __uint_as_float(f2tf(hv));
            // packed h write: k8 = ug>>3, mg=b>>4, lane=(b&7)*4+(u&3),
            // slot=((b>>3)&1) + 2*((u&7)>>2)
            int k8 = ug >> 3;
            int ln = (b & 7) * 4 + (uu & 3);
            int sl = ((b >> 3) & 1) + 2 * ((uu & 7) >> 2);
            g_hpack[(size_t)(t + 1) * 65536 + ((size_t)k8 * 4 + (b >> 4)) * 128 +
                    ln * 4 + sl] = hq;
            g_hist[((size_t)t * 64 + b) * 1024 + ug] = hq;
        }

        // grid barrier: red.release arrive + ld.acquire poll
        __syncthreads();
        if (tid == 0) {
            asm volatile("red.release.gpu.global.add.u32 [%0], 1;"
                         :: "l"(syncp) : "memory");
            const unsigned target = (unsigned)NCTA * (unsigned)(t + 1);
            unsigned v;
            do {
                asm volatile("ld.acquire.gpu.global.u32 %0, [%1];"
                             : "=r"(v) : "l"(syncp) : "memory");
            } while (v < target);
        }
        __syncthreads();
    }
}

// ---------------------------------------------------------------------------
extern "C" void kernel_launch(void* const* d_in, const int* in_sizes, int n_in,
                              void* d_out, int out_size)
{
    const float* emb  = (const float*)d_in[0];
    const float* W_ih = (const float*)d_in[1];
    const float* W_hh = (const float*)d_in[2];
    const float* b_ih = (const float*)d_in[3];
    const float* b_hh = (const float*)d_in[4];
    const float* W_fc = (const float*)d_in[5];
    const float* b_fc = (const float*)d_in[6];
    float* out = (float*)d_out;

    float *pre, *hist;
    cudaGetSymbolAddress((void**)&pre,  g_pre);
    cudaGetSymbolAddress((void**)&hist, g_hist);

    init_kernel<<<64, 1024>>>();

    // prepass: pre[t*64+b] = emb[b*256+t] @ W_ih^T + b_ih + b_hh   (perm=1)
    gemm_tf32<<<dim3(BT / 128, G4 / 128), 256>>>(
        emb, EMBED, W_ih, EMBED, pre, G4, EMBED, b_ih, b_hh, 1);

    cudaFuncSetAttribute(lstm_persistent,
                         cudaFuncAttributeMaxDynamicSharedMemorySize, SM_BYTES);
    lstm_persistent<<<NCTA, 256, SM_BYTES>>>(pre, W_hh);

    // fc: out[b*256+t] = hist[t*64+b] @ W_fc^T + b_fc   (perm=2)
    gemm_tf32<<<dim3(BT / 128, HIDDEN / 128), 256>>>(
        hist, HIDDEN, W_fc, HIDDEN, out, HIDDEN, HIDDEN, b_fc, nullptr, 2);
}

// round 13
// speedup vs baseline: 1.5000x; 1.5000x over previous
#include <cuda_runtime.h>
#include <cuda_fp16.h>

#define BATCH  64
#define SEQ    256
#define EMBED  512
#define HIDDEN 1024
#define G4     4096
#define BT     (BATCH * SEQ)
#define NCTA   128

// ---------------- scratch ----------------
// packed h (fp16): per t, uint4 entries [(ks*4 + mg)*32 + lane], 8 halves each
__device__ __align__(256) float  g_pre [(size_t)BT * G4];
__device__ __align__(256) __half g_hpk [(size_t)(SEQ + 1) * 65536];
__device__ __align__(256) float  g_hist[(size_t)BT * HIDDEN];
__device__ unsigned g_sync;

// ---------------- fp16 helpers ----------------
__device__ __forceinline__ unsigned pkh2(float lo, float hi) {
    __half2 h = __floats2half2_rn(lo, hi);
    return *(unsigned*)&h;
}
__device__ __forceinline__ void mma16(float* c, unsigned a0, unsigned a1,
                                      unsigned a2, unsigned a3,
                                      unsigned b0, unsigned b1) {
    asm volatile(
        "mma.sync.aligned.m16n8k16.row.col.f32.f16.f16.f32 "
        "{%0,%1,%2,%3},{%4,%5,%6,%7},{%8,%9},{%0,%1,%2,%3};"
        : "+f"(c[0]), "+f"(c[1]), "+f"(c[2]), "+f"(c[3])
        : "r"(a0), "r"(a1), "r"(a2), "r"(a3), "r"(b0), "r"(b1));
}

// ---------------------------------------------------------------------------
// fp16 GEMM: C[M,N] = A[M,K] @ B[N,K]^T (+bias1+bias2), fp32 accum.
// Block 128x128x32, 8 warps as 2(m) x 4(n), warp tile 64x32, m16n8k16.
// Smem holds half2 pairs; stride 20 words -> conflict-free frag reads.
// perm: 0 none; 1: out_row=(m&255)*64+(m>>8); 2: out_row=(m&63)*256+(m>>6).
// ---------------------------------------------------------------------------
__global__ __launch_bounds__(256, 2) void gemm_f16(
    const float* __restrict__ A, int lda,
    const float* __restrict__ B, int ldb,
    float* __restrict__ C, int ldc, int K,
    const float* __restrict__ bias1, const float* __restrict__ bias2,
    int perm)
{
    __shared__ unsigned As[128][20];   // [row][k-pair 0..15], pad 20
    __shared__ unsigned Bs[128][20];
    const int tid = threadIdx.x, w = tid >> 5, lane = tid & 31;
    const int g = lane >> 2, cq = lane & 3;
    const int wm = w >> 2;          // 0..1 : 64 m-rows
    const int wn = w & 3;           // 0..3 : 32 n-cols
    const long m0 = (long)blockIdx.x * 128, n0 = (long)blockIdx.y * 128;

    float acc[4][4][4];
#pragma unroll
    for (int mi = 0; mi < 4; mi++)
#pragma unroll
        for (int ni = 0; ni < 4; ni++)
#pragma unroll
            for (int e = 0; e < 4; e++) acc[mi][ni][e] = 0.f;

    const int srow = tid >> 3, scol = (tid & 7) * 4;

    for (int k0 = 0; k0 < K; k0 += 32) {
#pragma unroll
        for (int p = 0; p < 4; p++) {
            int r = p * 32 + srow;
            float4 v = *(const float4*)(A + (size_t)(m0 + r) * lda + k0 + scol);
            *(uint2*)&As[r][scol >> 1] =
                make_uint2(pkh2(v.x, v.y), pkh2(v.z, v.w));
        }
#pragma unroll
        for (int p = 0; p < 4; p++) {
            int r = p * 32 + srow;
            float4 v = *(const float4*)(B + (size_t)(n0 + r) * ldb + k0 + scol);
            *(uint2*)&Bs[r][scol >> 1] =
                make_uint2(pkh2(v.x, v.y), pkh2(v.z, v.w));
        }
        __syncthreads();
#pragma unroll
        for (int kk2 = 0; kk2 < 2; kk2++) {
            const int off = kk2 * 8;
            unsigned a[4][4], b[4][2];
#pragma unroll
            for (int mi = 0; mi < 4; mi++) {
                int rb = wm * 64 + mi * 16 + g;
                a[mi][0] = As[rb][off + cq];
                a[mi][1] = As[rb + 8][off + cq];
                a[mi][2] = As[rb][off + cq + 4];
                a[mi][3] = As[rb + 8][off + cq + 4];
            }
#pragma unroll
            for (int ni = 0; ni < 4; ni++) {
                int nb = wn * 32 + ni * 8 + g;
                b[ni][0] = Bs[nb][off + cq];
                b[ni][1] = Bs[nb][off + cq + 4];
            }
#pragma unroll
            for (int mi = 0; mi < 4; mi++)
#pragma unroll
                for (int ni = 0; ni < 4; ni++)
                    mma16(acc[mi][ni], a[mi][0], a[mi][1], a[mi][2], a[mi][3],
                          b[ni][0], b[ni][1]);
        }
        __syncthreads();
    }

#pragma unroll
    for (int ni = 0; ni < 4; ni++) {
        long col = n0 + wn * 32 + ni * 8 + 2 * cq;
        float bv0 = 0.f, bv1 = 0.f;
        if (bias1) { bv0 += bias1[col]; bv1 += bias1[col + 1]; }
        if (bias2) { bv0 += bias2[col]; bv1 += bias2[col + 1]; }
#pragma unroll
        for (int mi = 0; mi < 4; mi++) {
            long r0 = m0 + wm * 64 + mi * 16 + g;
            long r1 = r0 + 8;
            long p0 = (perm == 1) ? (r0 & 255) * 64 + (r0 >> 8)
                    : (perm == 2) ? (r0 & 63) * 256 + (r0 >> 6) : r0;
            long p1 = (perm == 1) ? (r1 & 255) * 64 + (r1 >> 8)
                    : (perm == 2) ? (r1 & 63) * 256 + (r1 >> 6) : r1;
            *(float2*)(C + p0 * ldc + col) =
                make_float2(acc[mi][ni][0] + bv0, acc[mi][ni][1] + bv1);
            *(float2*)(C + p1 * ldc + col) =
                make_float2(acc[mi][ni][2] + bv0, acc[mi][ni][3] + bv1);
        }
    }
}

// ---------------------------------------------------------------------------
__global__ void init_kernel()
{
    int idx = blockIdx.x * blockDim.x + threadIdx.x;   // 65536 threads
    g_hpk[idx] = __ushort_as_half((unsigned short)0);  // h_0 packed block = 0
    if (idx == 0) g_sync = 0;
}

// ---------------------------------------------------------------------------
// Persistent LSTM recurrence (fp16 operands, fp32 accum).
// 128 CTAs x 256 threads (1/SM). CTA j owns units [8j,8j+8) -> 32 gate rows
// (gate-grouped n = gate*8+u). Warps: 2 m-halves x 4 K-splits (K=256 each,
// 16 k16-steps). W_hh pre-packed in smem as fp16 B-fragments (LDS.64);
// h read from global in A-fragment-packed fp16 layout (1 coalesced LDG.128
// per fragment-pair entry, each h byte read once per CTA); K-partials reduced
// through smem; fused cell update; red.release/ld.acquire grid barrier.
// ---------------------------------------------------------------------------
#define P_STRIDE 34
#define WP_UINT2 8192                               // 64 KB packed W_hh
#define P_OFF    (WP_UINT2 * 8)
#define CS_OFF   (P_OFF + 4 * 64 * P_STRIDE * 4)
#define SMB      (CS_OFF + 512 * 4)                 // ~102 KB

__global__ __launch_bounds__(256, 1) void lstm_persistent(
    const float* __restrict__ pre, const float* __restrict__ Whh)
{
    extern __shared__ unsigned char smraw[];
    uint2* Wp2 = (uint2*)smraw;                     // B-frags: [(ks*4+ni)*32+lane]
    float* P   = (float*)(smraw + P_OFF);           // partials [4][64][34]
    float* csm = (float*)(smraw + CS_OFF);          // c state [512]

    const int j = blockIdx.x, tid = threadIdx.x;
    const int w = tid >> 5, lane = tid & 31;
    const int g = lane >> 2, cq = lane & 3;

    // ---- one-time: pack W_hh rows (gate-grouped) into fp16 B-fragments ----
    for (int idx = tid; idx < WP_UINT2; idx += 256) {
        int l  = idx & 31;
        int ni = (idx >> 5) & 3;
        int ks = idx >> 7;                          // 0..63
        int g2 = l >> 2, c2 = l & 3;
        const float* wr = Whh + (size_t)(ni * 1024 + 8 * j + g2) * 1024 +
                          ks * 16 + 2 * c2;
        Wp2[idx] = make_uint2(pkh2(wr[0], wr[1]), pkh2(wr[8], wr[9]));
    }
    csm[tid] = 0.f; csm[tid + 256] = 0.f;
    __syncthreads();

    const int mtw = w & 1;        // m-half: rows [mtw*32, +32)
    const int kh  = w >> 1;       // K-split: ks range [kh*16, +16)

    const int b0 = tid >> 3, u0 = tid & 7;
    const int b1 = (tid + 256) >> 3;

    unsigned* syncp = &g_sync;

    for (int t = 0; t < SEQ; t++) {
        // pre-gate prefetch (cold DRAM; consumed at end of step)
        const float* pp0 = pre + ((size_t)t * 64 + b0) * G4 + 8 * j + u0;
        const float* pp1 = pre + ((size_t)t * 64 + b1) * G4 + 8 * j + u0;
        float p0i = pp0[0], p0f = pp0[1024], p0g = pp0[2048], p0o = pp0[3072];
        float p1i = pp1[0], p1f = pp1[1024], p1g = pp1[2048], p1o = pp1[3072];

        float acc[2][4][4];
#pragma unroll
        for (int mi = 0; mi < 2; mi++)
#pragma unroll
            for (int ni = 0; ni < 4; ni++)
#pragma unroll
                for (int e = 0; e < 4; e++) acc[mi][ni][e] = 0.f;

        const uint4* Ab = (const uint4*)(g_hpk + (size_t)t * 65536);

        // chunk-4 double-buffered A fragments (8 LDG.128 per chunk)
        uint4 abuf[2][4][2];
#pragma unroll
        for (int q = 0; q < 4; q++)
#pragma unroll
            for (int mi = 0; mi < 2; mi++)
                abuf[0][q][mi] =
                    Ab[((kh * 16 + q) * 4 + mtw * 2 + mi) * 32 + lane];

        for (int c = 0; c < 4; c++) {
            if (c < 3) {
#pragma unroll
                for (int q = 0; q < 4; q++)
#pragma unroll
                    for (int mi = 0; mi < 2; mi++)
                        abuf[(c + 1) & 1][q][mi] =
                            Ab[((kh * 16 + (c + 1) * 4 + q) * 4 +
                                mtw * 2 + mi) * 32 + lane];
            }
#pragma unroll
            for (int q = 0; q < 4; q++) {
                int ks = kh * 16 + c * 4 + q;
                uint2 bf[4];
#pragma unroll
                for (int ni = 0; ni < 4; ni++)
                    bf[ni] = Wp2[(ks * 4 + ni) * 32 + lane];
#pragma unroll
                for (int mi = 0; mi < 2; mi++) {
                    uint4 a = abuf[c & 1][q][mi];
#pragma unroll
                    for (int ni = 0; ni < 4; ni++)
                        mma16(acc[mi][ni], a.x, a.y, a.z, a.w,
                              bf[ni].x, bf[ni].y);
                }
            }
        }

        // partials -> smem
#pragma unroll
        for (int mi = 0; mi < 2; mi++) {
            int r0 = mtw * 32 + mi * 16 + g;
#pragma unroll
            for (int ni = 0; ni < 4; ni++) {
                int col = ni * 8 + 2 * cq;
                *(float2*)&P[(kh * 64 + r0) * P_STRIDE + col] =
                    make_float2(acc[mi][ni][0], acc[mi][ni][1]);
                *(float2*)&P[(kh * 64 + r0 + 8) * P_STRIDE + col] =
                    make_float2(acc[mi][ni][2], acc[mi][ni][3]);
            }
        }
        __syncthreads();

        // fused cell update (2 units per thread)
#pragma unroll
        for (int q = 0; q < 2; q++) {
            int b = q ? b1 : b0;
            float gi = q ? p1i : p0i, gf = q ? p1f : p0f;
            float gg = q ? p1g : p0g, go = q ? p1o : p0o;
#pragma unroll
            for (int kk = 0; kk < 4; kk++) {
                const float* pr = &P[(kk * 64 + b) * P_STRIDE];
                gi += pr[u0]; gf += pr[8 + u0];
                gg += pr[16 + u0]; go += pr[24 + u0];
            }
            int ci = q * 256 + tid;
            float cc = csm[ci];
            float iv = 1.f / (1.f + __expf(-gi));
            float fv = 1.f / (1.f + __expf(-gf));
            float gv = tanhf(gg);
            float ov = 1.f / (1.f + __expf(-go));
            cc = fv * cc + iv * gv;
            csm[ci] = cc;
            float hv = ov * tanhf(cc);

            // packed fp16 h write for next step's A-fragments
            int ug = 8 * j + u0;
            int ks = ug >> 4, kk16 = ug & 15, mg = b >> 4;
            int ln = (b & 7) * 4 + ((kk16 & 7) >> 1);
            int hf = ((b >> 3) & 1) * 2 + ((kk16 >> 3) & 1) * 4 + (kk16 & 1);
            g_hpk[(size_t)(t + 1) * 65536 +
                  (((size_t)ks * 4 + mg) * 32 + ln) * 8 + hf] =
                __float2half_rn(hv);
            // full-precision h for the fc GEMM
            g_hist[((size_t)t * 64 + b) * 1024 + ug] = hv;
        }

        // grid barrier: red.release arrive + ld.acquire poll
        __syncthreads();
        if (tid == 0) {
            asm volatile("red.release.gpu.global.add.u32 [%0], 1;"
                         :: "l"(syncp) : "memory");
            const unsigned target = (unsigned)NCTA * (unsigned)(t + 1);
            unsigned v;
            do {
                asm volatile("ld.acquire.gpu.global.u32 %0, [%1];"
                             : "=r"(v) : "l"(syncp) : "memory");
            } while (v < target);
        }
        __syncthreads();
    }
}

// ---------------------------------------------------------------------------
extern "C" void kernel_launch(void* const* d_in, const int* in_sizes, int n_in,
                              void* d_out, int out_size)
{
    const float* emb  = (const float*)d_in[0];
    const float* W_ih = (const float*)d_in[1];
    const float* W_hh = (const float*)d_in[2];
    const float* b_ih = (const float*)d_in[3];
    const float* b_hh = (const float*)d_in[4];
    const float* W_fc = (const float*)d_in[5];
    const float* b_fc = (const float*)d_in[6];
    float* out = (float*)d_out;

    float *pre, *hist;
    cudaGetSymbolAddress((void**)&pre,  g_pre);
    cudaGetSymbolAddress((void**)&hist, g_hist);

    init_kernel<<<64, 1024>>>();

    // prepass: pre[t*64+b] = emb[b*256+t] @ W_ih^T + b_ih + b_hh   (perm=1)
    gemm_f16<<<dim3(BT / 128, G4 / 128), 256>>>(
        emb, EMBED, W_ih, EMBED, pre, G4, EMBED, b_ih, b_hh, 1);

    cudaFuncSetAttribute(lstm_persistent,
                         cudaFuncAttributeMaxDynamicSharedMemorySize, SMB);
    lstm_persistent<<<NCTA, 256, SMB>>>(pre, W_hh);

    // fc: out[b*256+t] = hist[t*64+b] @ W_fc^T + b_fc   (perm=2)
    gemm_f16<<<dim3(BT / 128, HIDDEN / 128), 256>>>(
        hist, HIDDEN, W_fc, HIDDEN, out, HIDDEN, HIDDEN, b_fc, nullptr, 2);
}